// round 3
// baseline (speedup 1.0000x reference)
#include <cuda_runtime.h>
#include <cstdint>

// ---------------------------------------------------------------------------
// B=8, N=128, S=100, F1=160
// Conv stack per image (1024 images):
//   L1: 1ch 100x100 -> conv3 98 -> pool 49  (10 ch)
//   L2: 10ch 49x49  -> conv3 47 -> pool 23
//   L3: 10ch 23x23  -> conv3 21 -> pool 10
//   L4: 10ch 10x10  -> conv3 8  -> pool 4   -> 160 features
// ---------------------------------------------------------------------------

#define NIMG 1024

__device__ float g_P1[NIMG * 10 * 49 * 49];
__device__ float g_P2[NIMG * 10 * 23 * 23];
__device__ float g_P3[NIMG * 10 * 10 * 10];
__device__ float g_Hf [NIMG * 160];
__device__ float g_dk1[NIMG * 256];
__device__ float g_dkf[NIMG * 512];
__device__ float g_xx [NIMG];
__device__ float g_K  [8 * 128 * 128];
__device__ float g_avg[NIMG * 160];
__device__ float g_H2 [NIMG * 160];
__device__ float g_H4 [NIMG * 160];
__device__ float g_H6 [NIMG * 160];

// ---------------------------------------------------------------------------
// Fused conv3x3 + ReLU + maxpool2x2, PAIRED: each thread computes TWO
// horizontally-adjacent pooled pixels for all 10 output channels.
// Conv region per thread: 2 rows x 4 cols x 10 oc = 80 accumulators.
// The 4x6 input patch is hoisted to registers, so every weight is loaded
// from SMEM exactly once per (ic) and feeds 8 FMAs -> FMA-bound inner loop.
// G images per block (item space = G * OS * PW).
// ---------------------------------------------------------------------------
template<int IC, int IS, int G, int BD>
__global__ __launch_bounds__(BD)
void conv_pool_pair(const float* __restrict__ in,
                    const float* __restrict__ w,
                    const float* __restrict__ bias,
                    float* __restrict__ out)
{
    constexpr int CS = IS - 2;
    constexpr int OS = CS / 2;
    constexpr int PW = (OS + 1) / 2;       // pooled-col pairs per row
    constexpr int IN = IC * IS * IS;
    constexpr int ITEMS = G * OS * PW;
    constexpr int WE = 10 * IC * 9;

    extern __shared__ float smem[];
    float* sIn = smem;            // G * IN
    float* sW  = smem + G * IN;   // WE
    float* sB  = sW + WE;         // 10

    const int img0 = blockIdx.x * G;

    for (int i = threadIdx.x; i < G * IN; i += BD) {
        const int g = i / IN;
        if (img0 + g < NIMG) sIn[i] = in[(size_t)(img0 + g) * IN + (i - g * IN)];
    }
    for (int i = threadIdx.x; i < WE; i += BD) sW[i] = w[i];
    if (threadIdx.x < 10) sB[threadIdx.x] = bias[threadIdx.x];
    __syncthreads();

    for (int item = threadIdx.x; item < ITEMS; item += BD) {
        const int g   = item / (OS * PW);
        const int rem = item - g * (OS * PW);
        const int oy  = rem / PW;
        const int px  = rem % PW;
        const int img = img0 + g;
        if (img >= NIMG) continue;

        const int iy0 = 2 * oy;
        const int ix0 = 4 * px;

        float acc[2][4][10];
        #pragma unroll
        for (int oc = 0; oc < 10; ++oc) {
            const float bv = sB[oc];
            #pragma unroll
            for (int dy = 0; dy < 2; ++dy)
                #pragma unroll
                for (int dx = 0; dx < 4; ++dx)
                    acc[dy][dx][oc] = bv;
        }

        const float* base = sIn + g * IN;
        for (int ic = 0; ic < IC; ++ic) {
            const float* rp = base + ic * IS * IS + iy0 * IS + ix0;
            float v[4][6];
            #pragma unroll
            for (int r = 0; r < 4; ++r)
                #pragma unroll
                for (int c = 0; c < 6; ++c)
                    v[r][c] = rp[r * IS + c];

            const float* wp = sW + ic * 9;
            #pragma unroll
            for (int ky = 0; ky < 3; ++ky) {
                #pragma unroll
                for (int kx = 0; kx < 3; ++kx) {
                    #pragma unroll
                    for (int oc = 0; oc < 10; ++oc) {
                        const float wv = wp[oc * IC * 9 + ky * 3 + kx];
                        #pragma unroll
                        for (int dy = 0; dy < 2; ++dy)
                            #pragma unroll
                            for (int dx = 0; dx < 4; ++dx)
                                acc[dy][dx][oc] += wv * v[ky + dy][kx + dx];
                    }
                }
            }
        }

        #pragma unroll
        for (int j = 0; j < 2; ++j) {
            const int ox = 2 * px + j;
            if (ox >= OS) break;
            #pragma unroll
            for (int oc = 0; oc < 10; ++oc) {
                float m = fmaxf(fmaxf(acc[0][2 * j][oc], acc[0][2 * j + 1][oc]),
                                fmaxf(acc[1][2 * j][oc], acc[1][2 * j + 1][oc]));
                m = fmaxf(m, 0.0f);
                out[((size_t)img * 10 + oc) * (OS * OS) + oy * OS + ox] = m;
            }
        }
    }
}

// ---------------------------------------------------------------------------
// Unpaired variant for tiny layers (L4): one pooled pixel per thread,
// G images per block, hoisted 4x4 input patch (each weight feeds 4 FMAs).
// ---------------------------------------------------------------------------
template<int IC, int IS, int G, int BD>
__global__ __launch_bounds__(BD)
void conv_pool_small(const float* __restrict__ in,
                     const float* __restrict__ w,
                     const float* __restrict__ bias,
                     float* __restrict__ out)
{
    constexpr int OS = (IS - 2) / 2;
    constexpr int IN = IC * IS * IS;
    constexpr int ITEMS = G * OS * OS;
    constexpr int WE = 10 * IC * 9;

    extern __shared__ float smem[];
    float* sIn = smem;
    float* sW  = smem + G * IN;
    float* sB  = sW + WE;

    const int img0 = blockIdx.x * G;
    for (int i = threadIdx.x; i < G * IN; i += BD) {
        const int g = i / IN;
        if (img0 + g < NIMG) sIn[i] = in[(size_t)(img0 + g) * IN + (i - g * IN)];
    }
    for (int i = threadIdx.x; i < WE; i += BD) sW[i] = w[i];
    if (threadIdx.x < 10) sB[threadIdx.x] = bias[threadIdx.x];
    __syncthreads();

    for (int item = threadIdx.x; item < ITEMS; item += BD) {
        const int g   = item / (OS * OS);
        const int pix = item - g * (OS * OS);
        const int oy  = pix / OS;
        const int ox  = pix % OS;
        const int img = img0 + g;
        if (img >= NIMG) continue;

        float acc[2][2][10];
        #pragma unroll
        for (int oc = 0; oc < 10; ++oc) {
            const float bv = sB[oc];
            acc[0][0][oc] = bv; acc[0][1][oc] = bv;
            acc[1][0][oc] = bv; acc[1][1][oc] = bv;
        }

        const float* base = sIn + g * IN;
        for (int ic = 0; ic < IC; ++ic) {
            const float* rp = base + ic * IS * IS + 2 * oy * IS + 2 * ox;
            float v[4][4];
            #pragma unroll
            for (int r = 0; r < 4; ++r)
                #pragma unroll
                for (int c = 0; c < 4; ++c)
                    v[r][c] = rp[r * IS + c];

            const float* wp = sW + ic * 9;
            #pragma unroll
            for (int ky = 0; ky < 3; ++ky)
                #pragma unroll
                for (int kx = 0; kx < 3; ++kx)
                    #pragma unroll
                    for (int oc = 0; oc < 10; ++oc) {
                        const float wv = wp[oc * IC * 9 + ky * 3 + kx];
                        #pragma unroll
                        for (int dy = 0; dy < 2; ++dy)
                            #pragma unroll
                            for (int dx = 0; dx < 2; ++dx)
                                acc[dy][dx][oc] += wv * v[ky + dy][kx + dx];
                    }
        }

        #pragma unroll
        for (int oc = 0; oc < 10; ++oc) {
            float m = fmaxf(fmaxf(acc[0][0][oc], acc[0][1][oc]),
                            fmaxf(acc[1][0][oc], acc[1][1][oc]));
            m = fmaxf(m, 0.0f);
            out[((size_t)img * 10 + oc) * (OS * OS) + oy * OS + ox] = m;
        }
    }
}

// ---------------------------------------------------------------------------
// Tiled SGEMM-NT:  C[M,N] = act( A[M,K] @ B[N,K]^T + bias[N] ), batched via z.
// ---------------------------------------------------------------------------
template<int BM, int BN, int TM, int TN, bool TANH, bool HASBIAS>
__global__ void gemm_nt_kernel(const float* __restrict__ A,
                               const float* __restrict__ B,
                               const float* __restrict__ bias,
                               float* __restrict__ C,
                               int M, int N, int K,
                               long long sA, long long sB, long long sC)
{
    constexpr int TX = BN / TN;
    __shared__ float As[16 * (BM + 1)];
    __shared__ float Bs[16 * (BN + 1)];

    const int tid = threadIdx.x;
    const int bz  = blockIdx.z;
    const float* Ab = A + bz * sA;
    const float* Bb = B + bz * sB;
    float* Cb = C + bz * sC;

    const int row0 = blockIdx.y * BM;
    const int col0 = blockIdx.x * BN;
    const int ty = tid / TX;
    const int tx = tid % TX;

    float acc[TM][TN] = {};

    for (int k0 = 0; k0 < K; k0 += 16) {
        for (int li = tid; li < BM * 16; li += blockDim.x) {
            const int r = li >> 4, kk = li & 15;
            const int gr = row0 + r;
            As[kk * (BM + 1) + r] = (gr < M) ? Ab[(size_t)gr * K + k0 + kk] : 0.0f;
        }
        for (int li = tid; li < BN * 16; li += blockDim.x) {
            const int r = li >> 4, kk = li & 15;
            const int gc = col0 + r;
            Bs[kk * (BN + 1) + r] = (gc < N) ? Bb[(size_t)gc * K + k0 + kk] : 0.0f;
        }
        __syncthreads();

        #pragma unroll
        for (int kk = 0; kk < 16; ++kk) {
            float a[TM], b[TN];
            #pragma unroll
            for (int i = 0; i < TM; ++i) a[i] = As[kk * (BM + 1) + ty * TM + i];
            #pragma unroll
            for (int j = 0; j < TN; ++j) b[j] = Bs[kk * (BN + 1) + tx * TN + j];
            #pragma unroll
            for (int i = 0; i < TM; ++i)
                #pragma unroll
                for (int j = 0; j < TN; ++j)
                    acc[i][j] += a[i] * b[j];
        }
        __syncthreads();
    }

    #pragma unroll
    for (int i = 0; i < TM; ++i) {
        const int gr = row0 + ty * TM + i;
        if (gr >= M) continue;
        #pragma unroll
        for (int j = 0; j < TN; ++j) {
            const int gc = col0 + tx * TN + j;
            if (gc >= N) continue;
            float v = acc[i][j];
            if (HASBIAS) v += bias[gc];
            if (TANH) v = tanhf(v);
            Cb[(size_t)gr * N + gc] = v;
        }
    }
}

// xx[r] = sum_k dkf[r,k]^2   (K = 512)
__global__ void rowsq_kernel(const float* __restrict__ x, float* __restrict__ xx)
{
    const int r = blockIdx.x;
    float s = 0.0f;
    for (int k = threadIdx.x; k < 512; k += 128) {
        float v = x[(size_t)r * 512 + k];
        s += v * v;
    }
    __shared__ float red[128];
    red[threadIdx.x] = s;
    __syncthreads();
    for (int st = 64; st > 0; st >>= 1) {
        if (threadIdx.x < st) red[threadIdx.x] += red[threadIdx.x + st];
        __syncthreads();
    }
    if (threadIdx.x == 0) xx[r] = red[0];
}

// K[n,m] = softmax_m((2*xy - xx[m]) / sigma)  (per-row constants dropped)
__global__ void softmax_kernel(float* __restrict__ xy,
                               const float* __restrict__ xx,
                               const float* __restrict__ sigma)
{
    const int row = blockIdx.x;
    const int b = row >> 7;
    const int t = threadIdx.x;
    const float inv_s = 1.0f / sigma[0];
    float* L = xy + (size_t)row * 128;

    float v = (2.0f * L[t] - xx[b * 128 + t]) * inv_s;

    __shared__ float red[128];
    red[t] = v;
    __syncthreads();
    for (int st = 64; st > 0; st >>= 1) {
        if (t < st) red[t] = fmaxf(red[t], red[t + st]);
        __syncthreads();
    }
    const float mx = red[0];
    __syncthreads();
    const float e = expf(v - mx);
    red[t] = e;
    __syncthreads();
    for (int st = 64; st > 0; st >>= 1) {
        if (t < st) red[t] += red[t + st];
        __syncthreads();
    }
    L[t] = e / red[0];
}

// ---------------------------------------------------------------------------
// Fused message-pass + residual-average:
//   out[b,n,t] = 0.5 * ( z[b,n,t] + sum_m K[b,n,m] * z[b,m,t] )
// Block handles 8 consecutive n rows (z reuse x8). grid (16, 8), 160 threads.
// ---------------------------------------------------------------------------
__global__ void mix_avg_kernel(const float* __restrict__ Kw,
                               const float* __restrict__ z,
                               float* __restrict__ out)
{
    const int b  = blockIdx.y;
    const int n0 = blockIdx.x * 8;
    const int t  = threadIdx.x;

    __shared__ float sK[8][128];
    const float* Kr = Kw + ((size_t)b * 128 + n0) * 128;
    for (int i = t; i < 8 * 128; i += 160) sK[i >> 7][i & 127] = Kr[i];
    __syncthreads();

    const float* zb = z + (size_t)b * 128 * 160;
    float acc[8] = {};
    #pragma unroll 4
    for (int m = 0; m < 128; ++m) {
        const float zv = zb[(size_t)m * 160 + t];
        #pragma unroll
        for (int j = 0; j < 8; ++j) acc[j] += sK[j][m] * zv;
    }
    #pragma unroll
    for (int j = 0; j < 8; ++j)
        out[((size_t)b * 128 + n0 + j) * 160 + t] =
            0.5f * (acc[j] + zb[(size_t)(n0 + j) * 160 + t]);
}

// out[b] = exp( sum_d max_n(H6[b,n,d]) * Wc[d] + bc )
__global__ void final_kernel(const float* __restrict__ H6,
                             const float* __restrict__ Wc,
                             const float* __restrict__ bc,
                             float* __restrict__ out)
{
    const int b = blockIdx.x;
    const int t = threadIdx.x;   // 160 threads = 5 warps
    float m = -3.0e38f;
    for (int n = 0; n < 128; ++n)
        m = fmaxf(m, H6[((size_t)b * 128 + n) * 160 + t]);
    float s = m * Wc[t];
    // warp reduce
    #pragma unroll
    for (int o = 16; o > 0; o >>= 1)
        s += __shfl_down_sync(0xFFFFFFFFu, s, o);
    __shared__ float red[5];
    if ((t & 31) == 0) red[t >> 5] = s;
    __syncthreads();
    if (t == 0) {
        float tot = red[0] + red[1] + red[2] + red[3] + red[4];
        out[b] = expf(tot + bc[0]);
    }
}

// ---------------------------------------------------------------------------
// Host launcher
// ---------------------------------------------------------------------------
extern "C" void kernel_launch(void* const* d_in, const int* in_sizes, int n_in,
                              void* d_out, int out_size)
{
    const float* H     = (const float*)d_in[0];
    const float* w1    = (const float*)d_in[1];
    const float* b1    = (const float*)d_in[2];
    const float* w2    = (const float*)d_in[3];
    const float* b2    = (const float*)d_in[4];
    const float* w3    = (const float*)d_in[5];
    const float* b3    = (const float*)d_in[6];
    const float* w4    = (const float*)d_in[7];
    const float* b4    = (const float*)d_in[8];
    const float* Wdk1  = (const float*)d_in[9];
    const float* bdk1  = (const float*)d_in[10];
    const float* Wdk2  = (const float*)d_in[11];
    const float* bdk2  = (const float*)d_in[12];
    const float* Wt1   = (const float*)d_in[13];
    const float* bt1   = (const float*)d_in[14];
    const float* Wt2   = (const float*)d_in[15];
    const float* bt2   = (const float*)d_in[16];
    const float* Wt3   = (const float*)d_in[17];
    const float* bt3   = (const float*)d_in[18];
    const float* sigma = (const float*)d_in[19];
    const float* Wc    = (const float*)d_in[20];
    const float* bc    = (const float*)d_in[21];

    float *p1, *p2, *p3, *hf, *dk1, *dkf, *xx, *Kp, *avg, *h2, *h4, *h6;
    cudaGetSymbolAddress((void**)&p1,  g_P1);
    cudaGetSymbolAddress((void**)&p2,  g_P2);
    cudaGetSymbolAddress((void**)&p3,  g_P3);
    cudaGetSymbolAddress((void**)&hf,  g_Hf);
    cudaGetSymbolAddress((void**)&dk1, g_dk1);
    cudaGetSymbolAddress((void**)&dkf, g_dkf);
    cudaGetSymbolAddress((void**)&xx,  g_xx);
    cudaGetSymbolAddress((void**)&Kp,  g_K);
    cudaGetSymbolAddress((void**)&avg, g_avg);
    cudaGetSymbolAddress((void**)&h2,  g_H2);
    cudaGetSymbolAddress((void**)&h4,  g_H4);
    cudaGetSymbolAddress((void**)&h6,  g_H6);

    // Shared-memory sizes
    const size_t smem1 = (1  * 100 * 100      + 10 * 1  * 9 + 10) * sizeof(float); //  40.4 KB
    const size_t smem2 = (10 * 49  * 49       + 10 * 10 * 9 + 10) * sizeof(float); //  99.7 KB
    const size_t smem3 = (5  * 10 * 23 * 23   + 10 * 10 * 9 + 10) * sizeof(float); // 109.4 KB
    const size_t smem4 = (16 * 10 * 10 * 10   + 10 * 10 * 9 + 10) * sizeof(float); //  67.6 KB
    cudaFuncSetAttribute(conv_pool_pair<10, 49, 1, 288>,
                         cudaFuncAttributeMaxDynamicSharedMemorySize, (int)smem2);
    cudaFuncSetAttribute(conv_pool_pair<10, 23, 5, 256>,
                         cudaFuncAttributeMaxDynamicSharedMemorySize, (int)smem3);
    cudaFuncSetAttribute(conv_pool_small<10, 10, 16, 256>,
                         cudaFuncAttributeMaxDynamicSharedMemorySize, (int)smem4);

    // ---- Conv stack ----
    conv_pool_pair<1, 100, 1, 256><<<NIMG, 256, smem1>>>(H,  w1, b1, p1);
    conv_pool_pair<10, 49, 1, 288><<<NIMG, 288, smem2>>>(p1, w2, b2, p2);
    conv_pool_pair<10, 23, 5, 256><<<(NIMG + 4) / 5, 256, smem3>>>(p2, w3, b3, p3);
    conv_pool_small<10, 10, 16, 256><<<NIMG / 16, 256, smem4>>>(p3, w4, b4, hf);

    // ---- Deep-kernel MLP ----
    gemm_nt_kernel<64, 64, 4, 4, true, true><<<dim3(4, 16, 1), 256>>>(
        hf, Wdk1, bdk1, dk1, 1024, 256, 160, 0, 0, 0);
    gemm_nt_kernel<64, 64, 4, 4, true, true><<<dim3(8, 16, 1), 256>>>(
        dk1, Wdk2, bdk2, dkf, 1024, 512, 256, 0, 0, 0);

    // ---- Attention matrix K (shared by all 3 message-passing rounds) ----
    rowsq_kernel<<<NIMG, 128>>>(dkf, xx);
    gemm_nt_kernel<32, 32, 2, 2, false, false><<<dim3(4, 4, 8), 256>>>(
        dkf, dkf, nullptr, Kp, 128, 128, 512,
        128LL * 512, 128LL * 512, 128LL * 128);
    softmax_kernel<<<NIMG, 128>>>(Kp, xx, sigma);

    dim3 mixg(16, 8);

    // ---- Round 1 ----
    mix_avg_kernel<<<mixg, 160>>>(Kp, hf, avg);
    gemm_nt_kernel<64, 64, 4, 4, true, true><<<dim3(3, 16, 1), 256>>>(
        avg, Wt1, bt1, h2, 1024, 160, 160, 0, 0, 0);

    // ---- Round 2 ----
    mix_avg_kernel<<<mixg, 160>>>(Kp, h2, avg);
    gemm_nt_kernel<64, 64, 4, 4, true, true><<<dim3(3, 16, 1), 256>>>(
        avg, Wt2, bt2, h4, 1024, 160, 160, 0, 0, 0);

    // ---- Round 3 ----
    mix_avg_kernel<<<mixg, 160>>>(Kp, h4, avg);
    gemm_nt_kernel<64, 64, 4, 4, true, true><<<dim3(3, 16, 1), 256>>>(
        avg, Wt3, bt3, h6, 1024, 160, 160, 0, 0, 0);

    // ---- Finish ----
    final_kernel<<<8, 160>>>(h6, Wc, bc, (float*)d_out);
}

// round 4
// speedup vs baseline: 1.0334x; 1.0334x over previous
#include <cuda_runtime.h>
#include <cstdint>

// ---------------------------------------------------------------------------
// B=8, N=128, S=100, F1=160
// Conv stack per image (1024 images):
//   L1: 1ch 100x100 -> conv3 98 -> pool 49  (10 ch)
//   L2: 10ch 49x49  -> conv3 47 -> pool 23
//   L3: 10ch 23x23  -> conv3 21 -> pool 10
//   L4: 10ch 10x10  -> conv3 8  -> pool 4   -> 160 features
// ---------------------------------------------------------------------------

#define NIMG 1024

__device__ float g_P1[NIMG * 10 * 49 * 49];
__device__ float g_P2[NIMG * 10 * 23 * 23];
__device__ float g_Hf [NIMG * 160];
__device__ float g_dk1[NIMG * 256];
__device__ float g_dkf[NIMG * 512];
__device__ float g_xx [NIMG];
__device__ float g_K  [8 * 128 * 128];
__device__ float g_avg[NIMG * 160];
__device__ float g_H2 [NIMG * 160];
__device__ float g_H4 [NIMG * 160];
__device__ float g_H6 [NIMG * 160];

// ---------------------------------------------------------------------------
// Paired conv3x3 + ReLU + maxpool2x2 microkernel body (shared by kernels):
// one thread computes TWO adjacent pooled pixels x 10 oc.
// acc[2][4][10]; input patch 4x6 hoisted to registers; each SMEM weight
// load feeds 8 FMAs -> FMA-pipe bound (720 FFMA vs 114 LDS per ic).
// ---------------------------------------------------------------------------

// L1: whole image per block (IC=1, IS=100, smem 40.4KB)
template<int IC, int IS, int BD>
__global__ __launch_bounds__(BD)
void conv_pool_pair(const float* __restrict__ in,
                    const float* __restrict__ w,
                    const float* __restrict__ bias,
                    float* __restrict__ out)
{
    constexpr int CS = IS - 2;
    constexpr int OS = CS / 2;
    constexpr int PW = (OS + 1) / 2;
    constexpr int IN = IC * IS * IS;
    constexpr int ITEMS = OS * PW;
    constexpr int WE = 10 * IC * 9;

    extern __shared__ float smem[];
    float* sIn = smem;
    float* sW  = smem + IN;
    float* sB  = sW + WE;

    const int img = blockIdx.x;
    const float* gIn = in + (size_t)img * IN;
    for (int i = threadIdx.x; i < IN; i += BD) sIn[i] = gIn[i];
    for (int i = threadIdx.x; i < WE; i += BD) sW[i] = w[i];
    if (threadIdx.x < 10) sB[threadIdx.x] = bias[threadIdx.x];
    __syncthreads();

    for (int item = threadIdx.x; item < ITEMS; item += BD) {
        const int oy = item / PW;
        const int px = item % PW;
        const int iy0 = 2 * oy;
        const int ix0 = 4 * px;

        float acc[2][4][10];
        #pragma unroll
        for (int oc = 0; oc < 10; ++oc) {
            const float bv = sB[oc];
            #pragma unroll
            for (int dy = 0; dy < 2; ++dy)
                #pragma unroll
                for (int dx = 0; dx < 4; ++dx) acc[dy][dx][oc] = bv;
        }

        #pragma unroll
        for (int ic = 0; ic < IC; ++ic) {
            const float* rp = sIn + ic * IS * IS + iy0 * IS + ix0;
            float v[4][6];
            #pragma unroll
            for (int r = 0; r < 4; ++r)
                #pragma unroll
                for (int c = 0; c < 6; ++c) v[r][c] = rp[r * IS + c];

            const float* wp = sW + ic * 9;
            #pragma unroll
            for (int ky = 0; ky < 3; ++ky)
                #pragma unroll
                for (int kx = 0; kx < 3; ++kx)
                    #pragma unroll
                    for (int oc = 0; oc < 10; ++oc) {
                        const float wv = wp[oc * IC * 9 + ky * 3 + kx];
                        #pragma unroll
                        for (int dy = 0; dy < 2; ++dy)
                            #pragma unroll
                            for (int dx = 0; dx < 4; ++dx)
                                acc[dy][dx][oc] += wv * v[ky + dy][kx + dx];
                    }
        }

        #pragma unroll
        for (int j = 0; j < 2; ++j) {
            const int ox = 2 * px + j;
            if (ox >= OS) break;
            #pragma unroll
            for (int oc = 0; oc < 10; ++oc) {
                float m = fmaxf(fmaxf(acc[0][2 * j][oc], acc[0][2 * j + 1][oc]),
                                fmaxf(acc[1][2 * j][oc], acc[1][2 * j + 1][oc]));
                out[((size_t)img * 10 + oc) * (OS * OS) + oy * OS + ox] =
                    fmaxf(m, 0.0f);
            }
        }
    }
}

// ---------------------------------------------------------------------------
// L2: image split into row bands -> 2 blocks per image (blockIdx.y = half).
// Band covers pooled rows [oy0, oy0+nr); loads input rows [2*oy0, 2*oy0+2nr+2).
// smem ~54.6KB -> 3 resident blocks/SM instead of 1.
// ---------------------------------------------------------------------------
template<int IC, int IS, int BD>
__global__ __launch_bounds__(BD)
void conv_pool_rows(const float* __restrict__ in,
                    const float* __restrict__ w,
                    const float* __restrict__ bias,
                    float* __restrict__ out)
{
    constexpr int CS = IS - 2;
    constexpr int OS = CS / 2;          // 23
    constexpr int PW = (OS + 1) / 2;    // 12
    constexpr int WE = 10 * IC * 9;
    constexpr int NR0 = (OS + 1) / 2;   // 12 rows in band 0

    const int half = blockIdx.y;
    const int oy0 = half ? NR0 : 0;
    const int nr  = half ? (OS - NR0) : NR0;     // 11 or 12
    const int inRows = 2 * nr + 2;               // 24 or 26
    const int maxRows = 2 * NR0 + 2;             // 26 (smem sizing)

    extern __shared__ float smem[];
    float* sIn = smem;                           // IC * maxRows * IS
    float* sW  = smem + IC * maxRows * IS;
    float* sB  = sW + WE;

    const int img = blockIdx.x;
    const int icStride = inRows * IS;
    const float* gIn = in + (size_t)img * IC * IS * IS + (size_t)(2 * oy0) * IS;

    const int total = IC * icStride;
    for (int i = threadIdx.x; i < total; i += BD) {
        const int ic = i / icStride;
        const int r  = i - ic * icStride;        // r = row*IS + col
        sIn[i] = gIn[ic * IS * IS + r];
    }
    for (int i = threadIdx.x; i < WE; i += BD) sW[i] = w[i];
    if (threadIdx.x < 10) sB[threadIdx.x] = bias[threadIdx.x];
    __syncthreads();

    const int ITEMS = nr * PW;
    for (int item = threadIdx.x; item < ITEMS; item += BD) {
        const int oyr = item / PW;
        const int px  = item % PW;
        const int iy0 = 2 * oyr;
        const int ix0 = 4 * px;
        const int oy  = oy0 + oyr;

        float acc[2][4][10];
        #pragma unroll
        for (int oc = 0; oc < 10; ++oc) {
            const float bv = sB[oc];
            #pragma unroll
            for (int dy = 0; dy < 2; ++dy)
                #pragma unroll
                for (int dx = 0; dx < 4; ++dx) acc[dy][dx][oc] = bv;
        }

        for (int ic = 0; ic < IC; ++ic) {
            const float* rp = sIn + ic * icStride + iy0 * IS + ix0;
            float v[4][6];
            #pragma unroll
            for (int r = 0; r < 4; ++r)
                #pragma unroll
                for (int c = 0; c < 6; ++c) v[r][c] = rp[r * IS + c];

            const float* wp = sW + ic * 9;
            #pragma unroll
            for (int ky = 0; ky < 3; ++ky)
                #pragma unroll
                for (int kx = 0; kx < 3; ++kx)
                    #pragma unroll
                    for (int oc = 0; oc < 10; ++oc) {
                        const float wv = wp[oc * IC * 9 + ky * 3 + kx];
                        #pragma unroll
                        for (int dy = 0; dy < 2; ++dy)
                            #pragma unroll
                            for (int dx = 0; dx < 4; ++dx)
                                acc[dy][dx][oc] += wv * v[ky + dy][kx + dx];
                    }
        }

        #pragma unroll
        for (int j = 0; j < 2; ++j) {
            const int ox = 2 * px + j;
            if (ox >= OS) break;
            #pragma unroll
            for (int oc = 0; oc < 10; ++oc) {
                float m = fmaxf(fmaxf(acc[0][2 * j][oc], acc[0][2 * j + 1][oc]),
                                fmaxf(acc[1][2 * j][oc], acc[1][2 * j + 1][oc]));
                out[((size_t)img * 10 + oc) * (OS * OS) + oy * OS + ox] =
                    fmaxf(m, 0.0f);
            }
        }
    }
}

// ---------------------------------------------------------------------------
// Fused L3 + L4: G=2 images per block. L3 (23->10) written to SMEM,
// L4 (10->4) consumes it directly -> no global round-trip, no tiny kernel.
// smem ~57.6KB, grid 512, BD=128 -> 3 resident blocks/SM.
// ---------------------------------------------------------------------------
template<int G, int BD>
__global__ __launch_bounds__(BD)
void conv34_fused(const float* __restrict__ in,
                  const float* __restrict__ w3,
                  const float* __restrict__ b3,
                  const float* __restrict__ w4,
                  const float* __restrict__ b4,
                  float* __restrict__ out)
{
    constexpr int IS = 23, OS = 10, PW = 5;     // L3
    constexpr int IN = 10 * IS * IS;            // 5290 per image
    constexpr int MID = 10 * OS * OS;           // 1000 per image

    extern __shared__ float smem[];
    float* sIn  = smem;                   // G*IN
    float* sW3  = sIn + G * IN;           // 900
    float* sB3  = sW3 + 900;              // 10
    float* sMid = sB3 + 10;               // G*MID
    float* sW4  = sMid + G * MID;         // 900
    float* sB4  = sW4 + 900;              // 10

    const int img0 = blockIdx.x * G;
    for (int i = threadIdx.x; i < G * IN; i += BD) {
        const int g = i / IN;
        sIn[i] = in[(size_t)(img0 + g) * IN + (i - g * IN)];
    }
    for (int i = threadIdx.x; i < 900; i += BD) { sW3[i] = w3[i]; sW4[i] = w4[i]; }
    if (threadIdx.x < 10) { sB3[threadIdx.x] = b3[threadIdx.x];
                            sB4[threadIdx.x] = b4[threadIdx.x]; }
    __syncthreads();

    // ---- Phase A: L3 (paired), items = G*10*5 ----
    for (int item = threadIdx.x; item < G * OS * PW; item += BD) {
        const int g   = item / (OS * PW);
        const int rem = item - g * (OS * PW);
        const int oy  = rem / PW;
        const int px  = rem % PW;
        const int iy0 = 2 * oy, ix0 = 4 * px;

        float acc[2][4][10];
        #pragma unroll
        for (int oc = 0; oc < 10; ++oc) {
            const float bv = sB3[oc];
            #pragma unroll
            for (int dy = 0; dy < 2; ++dy)
                #pragma unroll
                for (int dx = 0; dx < 4; ++dx) acc[dy][dx][oc] = bv;
        }

        const float* base = sIn + g * IN;
        for (int ic = 0; ic < 10; ++ic) {
            const float* rp = base + ic * IS * IS + iy0 * IS + ix0;
            float v[4][6];
            #pragma unroll
            for (int r = 0; r < 4; ++r)
                #pragma unroll
                for (int c = 0; c < 6; ++c) v[r][c] = rp[r * IS + c];

            const float* wp = sW3 + ic * 9;
            #pragma unroll
            for (int ky = 0; ky < 3; ++ky)
                #pragma unroll
                for (int kx = 0; kx < 3; ++kx)
                    #pragma unroll
                    for (int oc = 0; oc < 10; ++oc) {
                        const float wv = wp[oc * 90 + ky * 3 + kx];
                        #pragma unroll
                        for (int dy = 0; dy < 2; ++dy)
                            #pragma unroll
                            for (int dx = 0; dx < 4; ++dx)
                                acc[dy][dx][oc] += wv * v[ky + dy][kx + dx];
                    }
        }

        float* mid = sMid + g * MID;
        #pragma unroll
        for (int j = 0; j < 2; ++j) {
            const int ox = 2 * px + j;
            #pragma unroll
            for (int oc = 0; oc < 10; ++oc) {
                float m = fmaxf(fmaxf(acc[0][2 * j][oc], acc[0][2 * j + 1][oc]),
                                fmaxf(acc[1][2 * j][oc], acc[1][2 * j + 1][oc]));
                mid[oc * (OS * OS) + oy * OS + ox] = fmaxf(m, 0.0f);
            }
        }
    }
    __syncthreads();

    // ---- Phase B: L4 (10 -> 4x4), items = G*16, one pooled pixel each ----
    for (int item = threadIdx.x; item < G * 16; item += BD) {
        const int g   = item / 16;
        const int pix = item % 16;
        const int oy  = pix / 4, ox = pix % 4;

        float acc[2][2][10];
        #pragma unroll
        for (int oc = 0; oc < 10; ++oc) {
            const float bv = sB4[oc];
            acc[0][0][oc] = bv; acc[0][1][oc] = bv;
            acc[1][0][oc] = bv; acc[1][1][oc] = bv;
        }

        const float* mid = sMid + g * MID;
        #pragma unroll
        for (int ic = 0; ic < 10; ++ic) {
            const float* rp = mid + ic * (OS * OS) + 2 * oy * OS + 2 * ox;
            float v[4][4];
            #pragma unroll
            for (int r = 0; r < 4; ++r)
                #pragma unroll
                for (int c = 0; c < 4; ++c) v[r][c] = rp[r * OS + c];

            const float* wp = sW4 + ic * 9;
            #pragma unroll
            for (int ky = 0; ky < 3; ++ky)
                #pragma unroll
                for (int kx = 0; kx < 3; ++kx)
                    #pragma unroll
                    for (int oc = 0; oc < 10; ++oc) {
                        const float wv = wp[oc * 90 + ky * 3 + kx];
                        #pragma unroll
                        for (int dy = 0; dy < 2; ++dy)
                            #pragma unroll
                            for (int dx = 0; dx < 2; ++dx)
                                acc[dy][dx][oc] += wv * v[ky + dy][kx + dx];
                    }
        }

        #pragma unroll
        for (int oc = 0; oc < 10; ++oc) {
            float m = fmaxf(fmaxf(acc[0][0][oc], acc[0][1][oc]),
                            fmaxf(acc[1][0][oc], acc[1][1][oc]));
            out[(size_t)(img0 + g) * 160 + oc * 16 + pix] = fmaxf(m, 0.0f);
        }
    }
}

// ---------------------------------------------------------------------------
// Tiled SGEMM-NT:  C[M,N] = act( A[M,K] @ B[N,K]^T + bias[N] ), batched via z.
// ---------------------------------------------------------------------------
template<int BM, int BN, int TM, int TN, bool TANH, bool HASBIAS>
__global__ void gemm_nt_kernel(const float* __restrict__ A,
                               const float* __restrict__ B,
                               const float* __restrict__ bias,
                               float* __restrict__ C,
                               int M, int N, int K,
                               long long sA, long long sB, long long sC)
{
    constexpr int TX = BN / TN;
    __shared__ float As[16 * (BM + 1)];
    __shared__ float Bs[16 * (BN + 1)];

    const int tid = threadIdx.x;
    const int bz  = blockIdx.z;
    const float* Ab = A + bz * sA;
    const float* Bb = B + bz * sB;
    float* Cb = C + bz * sC;

    const int row0 = blockIdx.y * BM;
    const int col0 = blockIdx.x * BN;
    const int ty = tid / TX;
    const int tx = tid % TX;

    float acc[TM][TN] = {};

    for (int k0 = 0; k0 < K; k0 += 16) {
        for (int li = tid; li < BM * 16; li += blockDim.x) {
            const int r = li >> 4, kk = li & 15;
            const int gr = row0 + r;
            As[kk * (BM + 1) + r] = (gr < M) ? Ab[(size_t)gr * K + k0 + kk] : 0.0f;
        }
        for (int li = tid; li < BN * 16; li += blockDim.x) {
            const int r = li >> 4, kk = li & 15;
            const int gc = col0 + r;
            Bs[kk * (BN + 1) + r] = (gc < N) ? Bb[(size_t)gc * K + k0 + kk] : 0.0f;
        }
        __syncthreads();

        #pragma unroll
        for (int kk = 0; kk < 16; ++kk) {
            float a[TM], b[TN];
            #pragma unroll
            for (int i = 0; i < TM; ++i) a[i] = As[kk * (BM + 1) + ty * TM + i];
            #pragma unroll
            for (int j = 0; j < TN; ++j) b[j] = Bs[kk * (BN + 1) + tx * TN + j];
            #pragma unroll
            for (int i = 0; i < TM; ++i)
                #pragma unroll
                for (int j = 0; j < TN; ++j)
                    acc[i][j] += a[i] * b[j];
        }
        __syncthreads();
    }

    #pragma unroll
    for (int i = 0; i < TM; ++i) {
        const int gr = row0 + ty * TM + i;
        if (gr >= M) continue;
        #pragma unroll
        for (int j = 0; j < TN; ++j) {
            const int gc = col0 + tx * TN + j;
            if (gc >= N) continue;
            float v = acc[i][j];
            if (HASBIAS) v += bias[gc];
            if (TANH) v = tanhf(v);
            Cb[(size_t)gr * N + gc] = v;
        }
    }
}

// xx[r] = sum_k dkf[r,k]^2   (K = 512)
__global__ void rowsq_kernel(const float* __restrict__ x, float* __restrict__ xx)
{
    const int r = blockIdx.x;
    float s = 0.0f;
    for (int k = threadIdx.x; k < 512; k += 128) {
        float v = x[(size_t)r * 512 + k];
        s += v * v;
    }
    __shared__ float red[128];
    red[threadIdx.x] = s;
    __syncthreads();
    for (int st = 64; st > 0; st >>= 1) {
        if (threadIdx.x < st) red[threadIdx.x] += red[threadIdx.x + st];
        __syncthreads();
    }
    if (threadIdx.x == 0) xx[r] = red[0];
}

// K[n,m] = softmax_m((2*xy - xx[m]) / sigma)  (per-row constants dropped)
__global__ void softmax_kernel(float* __restrict__ xy,
                               const float* __restrict__ xx,
                               const float* __restrict__ sigma)
{
    const int row = blockIdx.x;
    const int b = row >> 7;
    const int t = threadIdx.x;
    const float inv_s = 1.0f / sigma[0];
    float* L = xy + (size_t)row * 128;

    float v = (2.0f * L[t] - xx[b * 128 + t]) * inv_s;

    __shared__ float red[128];
    red[t] = v;
    __syncthreads();
    for (int st = 64; st > 0; st >>= 1) {
        if (t < st) red[t] = fmaxf(red[t], red[t + st]);
        __syncthreads();
    }
    const float mx = red[0];
    __syncthreads();
    const float e = expf(v - mx);
    red[t] = e;
    __syncthreads();
    for (int st = 64; st > 0; st >>= 1) {
        if (t < st) red[t] += red[t + st];
        __syncthreads();
    }
    L[t] = e / red[0];
}

// out[b,n,t] = 0.5 * ( z[b,n,t] + sum_m K[b,n,m] * z[b,m,t] ), 8 rows/block
__global__ void mix_avg_kernel(const float* __restrict__ Kw,
                               const float* __restrict__ z,
                               float* __restrict__ out)
{
    const int b  = blockIdx.y;
    const int n0 = blockIdx.x * 8;
    const int t  = threadIdx.x;

    __shared__ float sK[8][128];
    const float* Kr = Kw + ((size_t)b * 128 + n0) * 128;
    for (int i = t; i < 8 * 128; i += 160) sK[i >> 7][i & 127] = Kr[i];
    __syncthreads();

    const float* zb = z + (size_t)b * 128 * 160;
    float acc[8] = {};
    #pragma unroll 4
    for (int m = 0; m < 128; ++m) {
        const float zv = zb[(size_t)m * 160 + t];
        #pragma unroll
        for (int j = 0; j < 8; ++j) acc[j] += sK[j][m] * zv;
    }
    #pragma unroll
    for (int j = 0; j < 8; ++j)
        out[((size_t)b * 128 + n0 + j) * 160 + t] =
            0.5f * (acc[j] + zb[(size_t)(n0 + j) * 160 + t]);
}

// out[b] = exp( sum_d max_n(H6[b,n,d]) * Wc[d] + bc )
__global__ void final_kernel(const float* __restrict__ H6,
                             const float* __restrict__ Wc,
                             const float* __restrict__ bc,
                             float* __restrict__ out)
{
    const int b = blockIdx.x;
    const int t = threadIdx.x;   // 160 threads = 5 warps
    float m = -3.0e38f;
    for (int n = 0; n < 128; ++n)
        m = fmaxf(m, H6[((size_t)b * 128 + n) * 160 + t]);
    float s = m * Wc[t];
    #pragma unroll
    for (int o = 16; o > 0; o >>= 1)
        s += __shfl_down_sync(0xFFFFFFFFu, s, o);
    __shared__ float red[5];
    if ((t & 31) == 0) red[t >> 5] = s;
    __syncthreads();
    if (t == 0) {
        float tot = red[0] + red[1] + red[2] + red[3] + red[4];
        out[b] = expf(tot + bc[0]);
    }
}

// ---------------------------------------------------------------------------
// Host launcher
// ---------------------------------------------------------------------------
extern "C" void kernel_launch(void* const* d_in, const int* in_sizes, int n_in,
                              void* d_out, int out_size)
{
    const float* H     = (const float*)d_in[0];
    const float* w1    = (const float*)d_in[1];
    const float* b1    = (const float*)d_in[2];
    const float* w2    = (const float*)d_in[3];
    const float* b2    = (const float*)d_in[4];
    const float* w3    = (const float*)d_in[5];
    const float* b3    = (const float*)d_in[6];
    const float* w4    = (const float*)d_in[7];
    const float* b4    = (const float*)d_in[8];
    const float* Wdk1  = (const float*)d_in[9];
    const float* bdk1  = (const float*)d_in[10];
    const float* Wdk2  = (const float*)d_in[11];
    const float* bdk2  = (const float*)d_in[12];
    const float* Wt1   = (const float*)d_in[13];
    const float* bt1   = (const float*)d_in[14];
    const float* Wt2   = (const float*)d_in[15];
    const float* bt2   = (const float*)d_in[16];
    const float* Wt3   = (const float*)d_in[17];
    const float* bt3   = (const float*)d_in[18];
    const float* sigma = (const float*)d_in[19];
    const float* Wc    = (const float*)d_in[20];
    const float* bc    = (const float*)d_in[21];

    float *p1, *p2, *hf, *dk1, *dkf, *xx, *Kp, *avg, *h2, *h4, *h6;
    cudaGetSymbolAddress((void**)&p1,  g_P1);
    cudaGetSymbolAddress((void**)&p2,  g_P2);
    cudaGetSymbolAddress((void**)&hf,  g_Hf);
    cudaGetSymbolAddress((void**)&dk1, g_dk1);
    cudaGetSymbolAddress((void**)&dkf, g_dkf);
    cudaGetSymbolAddress((void**)&xx,  g_xx);
    cudaGetSymbolAddress((void**)&Kp,  g_K);
    cudaGetSymbolAddress((void**)&avg, g_avg);
    cudaGetSymbolAddress((void**)&h2,  g_H2);
    cudaGetSymbolAddress((void**)&h4,  g_H4);
    cudaGetSymbolAddress((void**)&h6,  g_H6);

    const size_t smem1 = (1 * 100 * 100 + 90 + 10) * sizeof(float);          // 40.4 KB
    const size_t smem2 = (10 * 26 * 49 + 900 + 10) * sizeof(float);          // 54.6 KB
    const size_t smemf = (2 * 10 * 23 * 23 + 900 + 10 + 2 * 1000 + 900 + 10)
                         * sizeof(float);                                     // 57.6 KB
    cudaFuncSetAttribute(conv_pool_rows<10, 49, 160>,
                         cudaFuncAttributeMaxDynamicSharedMemorySize, (int)smem2);
    cudaFuncSetAttribute(conv34_fused<2, 128>,
                         cudaFuncAttributeMaxDynamicSharedMemorySize, (int)smemf);

    // ---- Conv stack ----
    conv_pool_pair<1, 100, 256><<<NIMG, 256, smem1>>>(H, w1, b1, p1);
    conv_pool_rows<10, 49, 160><<<dim3(NIMG, 2), 160, smem2>>>(p1, w2, b2, p2);
    conv34_fused<2, 128><<<NIMG / 2, 128, smemf>>>(p2, w3, b3, w4, b4, hf);

    // ---- Deep-kernel MLP ----
    gemm_nt_kernel<64, 64, 4, 4, true, true><<<dim3(4, 16, 1), 256>>>(
        hf, Wdk1, bdk1, dk1, 1024, 256, 160, 0, 0, 0);
    gemm_nt_kernel<64, 64, 4, 4, true, true><<<dim3(8, 16, 1), 256>>>(
        dk1, Wdk2, bdk2, dkf, 1024, 512, 256, 0, 0, 0);

    // ---- Attention matrix K (shared by all 3 message-passing rounds) ----
    rowsq_kernel<<<NIMG, 128>>>(dkf, xx);
    gemm_nt_kernel<32, 32, 2, 2, false, false><<<dim3(4, 4, 8), 256>>>(
        dkf, dkf, nullptr, Kp, 128, 128, 512,
        128LL * 512, 128LL * 512, 128LL * 128);
    softmax_kernel<<<NIMG, 128>>>(Kp, xx, sigma);

    dim3 mixg(16, 8);

    // ---- Round 1 ----
    mix_avg_kernel<<<mixg, 160>>>(Kp, hf, avg);
    gemm_nt_kernel<64, 64, 4, 4, true, true><<<dim3(3, 16, 1), 256>>>(
        avg, Wt1, bt1, h2, 1024, 160, 160, 0, 0, 0);

    // ---- Round 2 ----
    mix_avg_kernel<<<mixg, 160>>>(Kp, h2, avg);
    gemm_nt_kernel<64, 64, 4, 4, true, true><<<dim3(3, 16, 1), 256>>>(
        avg, Wt2, bt2, h4, 1024, 160, 160, 0, 0, 0);

    // ---- Round 3 ----
    mix_avg_kernel<<<mixg, 160>>>(Kp, h4, avg);
    gemm_nt_kernel<64, 64, 4, 4, true, true><<<dim3(3, 16, 1), 256>>>(
        avg, Wt3, bt3, h6, 1024, 160, 160, 0, 0, 0);

    // ---- Finish ----
    final_kernel<<<8, 160>>>(h6, Wc, bc, (float*)d_out);
}

// round 5
// speedup vs baseline: 1.3746x; 1.3302x over previous
#include <cuda_runtime.h>
#include <cstdint>

// ---------------------------------------------------------------------------
// B=8, N=128, S=100, F1=160
// Conv stack per image (1024 images):
//   L1: 1ch 100x100 -> conv3 98 -> pool 49  (10 ch)
//   L2: 10ch 49x49  -> conv3 47 -> pool 23
//   L3: 10ch 23x23  -> conv3 21 -> pool 10
//   L4: 10ch 10x10  -> conv3 8  -> pool 4   -> 160 features
// ---------------------------------------------------------------------------

#define NIMG 1024

__device__ float g_P1[NIMG * 10 * 49 * 49];
__device__ float g_P2[NIMG * 10 * 23 * 23];
__device__ float g_Hf [NIMG * 160];
__device__ float g_dk1[NIMG * 256];
__device__ float g_dkf[NIMG * 512];
__device__ float g_xx [NIMG];
__device__ float g_K  [8 * 128 * 128];
__device__ float g_avg[NIMG * 160];
__device__ float g_H2 [NIMG * 160];
__device__ float g_H4 [NIMG * 160];
__device__ float g_H6 [NIMG * 160];

// ---------------------------------------------------------------------------
// Paired conv3x3 + ReLU + maxpool2x2 microkernel. Each thread computes TWO
// adjacent pooled pixels. Output channels processed in TWO GROUPS OF 5
// (non-unrolled group loop) so live accumulators = 40 + 24-reg patch -> no
// register spill. Each weight LDS feeds 8 FMAs.
// ---------------------------------------------------------------------------

// L1: whole image per block (IC=1, IS=100)
template<int IC, int IS, int BD>
__global__ __launch_bounds__(BD, 2)
void conv_pool_pair(const float* __restrict__ in,
                    const float* __restrict__ w,
                    const float* __restrict__ bias,
                    float* __restrict__ out)
{
    constexpr int OS = (IS - 2) / 2;
    constexpr int PW = (OS + 1) / 2;
    constexpr int IN = IC * IS * IS;
    constexpr int ITEMS = OS * PW;
    constexpr int WE = 10 * IC * 9;

    extern __shared__ float smem[];
    float* sIn = smem;
    float* sW  = smem + IN;
    float* sB  = sW + WE;

    const int img = blockIdx.x;
    const float* gIn = in + (size_t)img * IN;
    for (int i = threadIdx.x; i < IN; i += BD) sIn[i] = gIn[i];
    for (int i = threadIdx.x; i < WE; i += BD) sW[i] = w[i];
    if (threadIdx.x < 10) sB[threadIdx.x] = bias[threadIdx.x];
    __syncthreads();

    for (int item = threadIdx.x; item < ITEMS; item += BD) {
        const int oy = item / PW;
        const int px = item % PW;
        const int iy0 = 2 * oy;
        const int ix0 = 4 * px;

        #pragma unroll 1
        for (int og = 0; og < 2; ++og) {
            float acc[2][4][5];
            #pragma unroll
            for (int oc = 0; oc < 5; ++oc) {
                const float bv = sB[og * 5 + oc];
                #pragma unroll
                for (int dy = 0; dy < 2; ++dy)
                    #pragma unroll
                    for (int dx = 0; dx < 4; ++dx) acc[dy][dx][oc] = bv;
            }

            #pragma unroll 1
            for (int ic = 0; ic < IC; ++ic) {
                const float* rp = sIn + ic * IS * IS + iy0 * IS + ix0;
                float v[4][6];
                #pragma unroll
                for (int r = 0; r < 4; ++r)
                    #pragma unroll
                    for (int c = 0; c < 6; ++c) v[r][c] = rp[r * IS + c];

                const float* wp = sW + (og * 5) * IC * 9 + ic * 9;
                #pragma unroll
                for (int ky = 0; ky < 3; ++ky)
                    #pragma unroll
                    for (int kx = 0; kx < 3; ++kx)
                        #pragma unroll
                        for (int oc = 0; oc < 5; ++oc) {
                            const float wv = wp[oc * IC * 9 + ky * 3 + kx];
                            #pragma unroll
                            for (int dy = 0; dy < 2; ++dy)
                                #pragma unroll
                                for (int dx = 0; dx < 4; ++dx)
                                    acc[dy][dx][oc] += wv * v[ky + dy][kx + dx];
                        }
            }

            #pragma unroll
            for (int j = 0; j < 2; ++j) {
                const int ox = 2 * px + j;
                if (ox >= OS) break;
                #pragma unroll
                for (int oc = 0; oc < 5; ++oc) {
                    float m = fmaxf(fmaxf(acc[0][2 * j][oc], acc[0][2 * j + 1][oc]),
                                    fmaxf(acc[1][2 * j][oc], acc[1][2 * j + 1][oc]));
                    out[((size_t)img * 10 + og * 5 + oc) * (OS * OS) + oy * OS + ox]
                        = fmaxf(m, 0.0f);
                }
            }
        }
    }
}

// ---------------------------------------------------------------------------
// L2: image split into 2 row bands (blockIdx.y), oc-split groups of 5.
// ---------------------------------------------------------------------------
template<int IC, int IS, int BD>
__global__ __launch_bounds__(BD, 4)
void conv_pool_rows(const float* __restrict__ in,
                    const float* __restrict__ w,
                    const float* __restrict__ bias,
                    float* __restrict__ out)
{
    constexpr int OS = (IS - 2) / 2;    // 23
    constexpr int PW = (OS + 1) / 2;    // 12
    constexpr int WE = 10 * IC * 9;
    constexpr int NR0 = (OS + 1) / 2;   // 12

    const int half = blockIdx.y;
    const int oy0 = half ? NR0 : 0;
    const int nr  = half ? (OS - NR0) : NR0;
    const int inRows = 2 * nr + 2;

    extern __shared__ float smem[];
    float* sIn = smem;                          // IC * 26 * IS (sized at launch)
    float* sW  = smem + IC * (2 * NR0 + 2) * IS;
    float* sB  = sW + WE;

    const int img = blockIdx.x;
    const int icStride = inRows * IS;
    const float* gIn = in + (size_t)img * IC * IS * IS + (size_t)(2 * oy0) * IS;

    const int total = IC * icStride;
    for (int i = threadIdx.x; i < total; i += BD) {
        const int ic = i / icStride;
        sIn[i] = gIn[ic * IS * IS + (i - ic * icStride)];
    }
    for (int i = threadIdx.x; i < WE; i += BD) sW[i] = w[i];
    if (threadIdx.x < 10) sB[threadIdx.x] = bias[threadIdx.x];
    __syncthreads();

    const int ITEMS = nr * PW;
    for (int item = threadIdx.x; item < ITEMS; item += BD) {
        const int oyr = item / PW;
        const int px  = item % PW;
        const int iy0 = 2 * oyr;
        const int ix0 = 4 * px;
        const int oy  = oy0 + oyr;

        #pragma unroll 1
        for (int og = 0; og < 2; ++og) {
            float acc[2][4][5];
            #pragma unroll
            for (int oc = 0; oc < 5; ++oc) {
                const float bv = sB[og * 5 + oc];
                #pragma unroll
                for (int dy = 0; dy < 2; ++dy)
                    #pragma unroll
                    for (int dx = 0; dx < 4; ++dx) acc[dy][dx][oc] = bv;
            }

            #pragma unroll 1
            for (int ic = 0; ic < IC; ++ic) {
                const float* rp = sIn + ic * icStride + iy0 * IS + ix0;
                float v[4][6];
                #pragma unroll
                for (int r = 0; r < 4; ++r)
                    #pragma unroll
                    for (int c = 0; c < 6; ++c) v[r][c] = rp[r * IS + c];

                const float* wp = sW + (og * 5) * IC * 9 + ic * 9;
                #pragma unroll
                for (int ky = 0; ky < 3; ++ky)
                    #pragma unroll
                    for (int kx = 0; kx < 3; ++kx)
                        #pragma unroll
                        for (int oc = 0; oc < 5; ++oc) {
                            const float wv = wp[oc * IC * 9 + ky * 3 + kx];
                            #pragma unroll
                            for (int dy = 0; dy < 2; ++dy)
                                #pragma unroll
                                for (int dx = 0; dx < 4; ++dx)
                                    acc[dy][dx][oc] += wv * v[ky + dy][kx + dx];
                        }
            }

            #pragma unroll
            for (int j = 0; j < 2; ++j) {
                const int ox = 2 * px + j;
                if (ox >= OS) break;
                #pragma unroll
                for (int oc = 0; oc < 5; ++oc) {
                    float m = fmaxf(fmaxf(acc[0][2 * j][oc], acc[0][2 * j + 1][oc]),
                                    fmaxf(acc[1][2 * j][oc], acc[1][2 * j + 1][oc]));
                    out[((size_t)img * 10 + og * 5 + oc) * (OS * OS) + oy * OS + ox]
                        = fmaxf(m, 0.0f);
                }
            }
        }
    }
}

// ---------------------------------------------------------------------------
// Fused L3 + L4 (G=2 images/block), oc-split groups of 5 in both phases.
// ---------------------------------------------------------------------------
template<int G, int BD>
__global__ __launch_bounds__(BD, 3)
void conv34_fused(const float* __restrict__ in,
                  const float* __restrict__ w3,
                  const float* __restrict__ b3,
                  const float* __restrict__ w4,
                  const float* __restrict__ b4,
                  float* __restrict__ out)
{
    constexpr int IS = 23, OS = 10, PW = 5;
    constexpr int IN = 10 * IS * IS;
    constexpr int MID = 10 * OS * OS;

    extern __shared__ float smem[];
    float* sIn  = smem;
    float* sW3  = sIn + G * IN;
    float* sB3  = sW3 + 900;
    float* sMid = sB3 + 10;
    float* sW4  = sMid + G * MID;
    float* sB4  = sW4 + 900;

    const int img0 = blockIdx.x * G;
    for (int i = threadIdx.x; i < G * IN; i += BD) {
        const int g = i / IN;
        sIn[i] = in[(size_t)(img0 + g) * IN + (i - g * IN)];
    }
    for (int i = threadIdx.x; i < 900; i += BD) { sW3[i] = w3[i]; sW4[i] = w4[i]; }
    if (threadIdx.x < 10) { sB3[threadIdx.x] = b3[threadIdx.x];
                            sB4[threadIdx.x] = b4[threadIdx.x]; }
    __syncthreads();

    // ---- Phase A: L3 paired ----
    for (int item = threadIdx.x; item < G * OS * PW; item += BD) {
        const int g   = item / (OS * PW);
        const int rem = item - g * (OS * PW);
        const int oy  = rem / PW;
        const int px  = rem % PW;
        const int iy0 = 2 * oy, ix0 = 4 * px;
        const float* base = sIn + g * IN;
        float* mid = sMid + g * MID;

        #pragma unroll 1
        for (int og = 0; og < 2; ++og) {
            float acc[2][4][5];
            #pragma unroll
            for (int oc = 0; oc < 5; ++oc) {
                const float bv = sB3[og * 5 + oc];
                #pragma unroll
                for (int dy = 0; dy < 2; ++dy)
                    #pragma unroll
                    for (int dx = 0; dx < 4; ++dx) acc[dy][dx][oc] = bv;
            }

            #pragma unroll 1
            for (int ic = 0; ic < 10; ++ic) {
                const float* rp = base + ic * IS * IS + iy0 * IS + ix0;
                float v[4][6];
                #pragma unroll
                for (int r = 0; r < 4; ++r)
                    #pragma unroll
                    for (int c = 0; c < 6; ++c) v[r][c] = rp[r * IS + c];

                const float* wp = sW3 + (og * 5) * 90 + ic * 9;
                #pragma unroll
                for (int ky = 0; ky < 3; ++ky)
                    #pragma unroll
                    for (int kx = 0; kx < 3; ++kx)
                        #pragma unroll
                        for (int oc = 0; oc < 5; ++oc) {
                            const float wv = wp[oc * 90 + ky * 3 + kx];
                            #pragma unroll
                            for (int dy = 0; dy < 2; ++dy)
                                #pragma unroll
                                for (int dx = 0; dx < 4; ++dx)
                                    acc[dy][dx][oc] += wv * v[ky + dy][kx + dx];
                        }
            }

            #pragma unroll
            for (int j = 0; j < 2; ++j) {
                const int ox = 2 * px + j;
                #pragma unroll
                for (int oc = 0; oc < 5; ++oc) {
                    float m = fmaxf(fmaxf(acc[0][2 * j][oc], acc[0][2 * j + 1][oc]),
                                    fmaxf(acc[1][2 * j][oc], acc[1][2 * j + 1][oc]));
                    mid[(og * 5 + oc) * (OS * OS) + oy * OS + ox] = fmaxf(m, 0.0f);
                }
            }
        }
    }
    __syncthreads();

    // ---- Phase B: L4, one pooled pixel/thread ----
    for (int item = threadIdx.x; item < G * 16; item += BD) {
        const int g   = item / 16;
        const int pix = item % 16;
        const int oy  = pix / 4, ox = pix % 4;
        const float* mid = sMid + g * MID;

        #pragma unroll 1
        for (int og = 0; og < 2; ++og) {
            float acc[2][2][5];
            #pragma unroll
            for (int oc = 0; oc < 5; ++oc) {
                const float bv = sB4[og * 5 + oc];
                acc[0][0][oc] = bv; acc[0][1][oc] = bv;
                acc[1][0][oc] = bv; acc[1][1][oc] = bv;
            }

            #pragma unroll 1
            for (int ic = 0; ic < 10; ++ic) {
                const float* rp = mid + ic * (OS * OS) + 2 * oy * OS + 2 * ox;
                float v[4][4];
                #pragma unroll
                for (int r = 0; r < 4; ++r)
                    #pragma unroll
                    for (int c = 0; c < 4; ++c) v[r][c] = rp[r * OS + c];

                const float* wp = sW4 + (og * 5) * 90 + ic * 9;
                #pragma unroll
                for (int ky = 0; ky < 3; ++ky)
                    #pragma unroll
                    for (int kx = 0; kx < 3; ++kx)
                        #pragma unroll
                        for (int oc = 0; oc < 5; ++oc) {
                            const float wv = wp[oc * 90 + ky * 3 + kx];
                            #pragma unroll
                            for (int dy = 0; dy < 2; ++dy)
                                #pragma unroll
                                for (int dx = 0; dx < 2; ++dx)
                                    acc[dy][dx][oc] += wv * v[ky + dy][kx + dx];
                        }
            }

            #pragma unroll
            for (int oc = 0; oc < 5; ++oc) {
                float m = fmaxf(fmaxf(acc[0][0][oc], acc[0][1][oc]),
                                fmaxf(acc[1][0][oc], acc[1][1][oc]));
                out[(size_t)(img0 + g) * 160 + (og * 5 + oc) * 16 + pix]
                    = fmaxf(m, 0.0f);
            }
        }
    }
}

// ---------------------------------------------------------------------------
// Small-matrix SGEMM-NT: C[M,N] = act(A[M,K] @ B[N,K]^T + bias).
// 32x32 tile, 64 threads, 4x4 microtile, K-chunk 16. High block count ->
// latency hidden by block-level parallelism. All dims divide exactly.
// ---------------------------------------------------------------------------
template<bool TANH, bool HASBIAS>
__global__ __launch_bounds__(64)
void gemm32(const float* __restrict__ A, const float* __restrict__ B,
            const float* __restrict__ bias, float* __restrict__ C,
            int M, int N, int K,
            long long sA, long long sB, long long sC)
{
    __shared__ float As[16][33];
    __shared__ float Bs[16][33];

    const int tid = threadIdx.x;
    const int ty = tid >> 3;          // 0..7
    const int tx = tid & 7;           // 0..7
    const int lrow = tid >> 4;        // 0..3
    const int lk   = tid & 15;        // 0..15

    const int row0 = blockIdx.y * 32;
    const int col0 = blockIdx.x * 32;
    const float* Ab = A + blockIdx.z * sA + (size_t)row0 * K;
    const float* Bb = B + blockIdx.z * sB + (size_t)col0 * K;
    float* Cb = C + blockIdx.z * sC;

    float acc[4][4] = {};

    for (int k0 = 0; k0 < K; k0 += 16) {
        #pragma unroll
        for (int p = 0; p < 8; ++p) {
            const int row = p * 4 + lrow;
            As[lk][row] = Ab[(size_t)row * K + k0 + lk];
            Bs[lk][row] = Bb[(size_t)row * K + k0 + lk];
        }
        __syncthreads();

        #pragma unroll
        for (int kk = 0; kk < 16; ++kk) {
            float a[4], b[4];
            #pragma unroll
            for (int i = 0; i < 4; ++i) a[i] = As[kk][ty * 4 + i];
            #pragma unroll
            for (int j = 0; j < 4; ++j) b[j] = Bs[kk][tx * 4 + j];
            #pragma unroll
            for (int i = 0; i < 4; ++i)
                #pragma unroll
                for (int j = 0; j < 4; ++j)
                    acc[i][j] += a[i] * b[j];
        }
        __syncthreads();
    }

    #pragma unroll
    for (int i = 0; i < 4; ++i) {
        const int gr = row0 + ty * 4 + i;
        #pragma unroll
        for (int j = 0; j < 4; ++j) {
            const int gc = col0 + tx * 4 + j;
            float v = acc[i][j];
            if (HASBIAS) v += bias[gc];
            if (TANH) v = tanhf(v);
            Cb[(size_t)gr * N + gc] = v;
        }
    }
}

// xx[r] = sum_k dkf[r,k]^2   (K = 512)
__global__ void rowsq_kernel(const float* __restrict__ x, float* __restrict__ xx)
{
    const int r = blockIdx.x;
    float s = 0.0f;
    for (int k = threadIdx.x; k < 512; k += 128) {
        float v = x[(size_t)r * 512 + k];
        s += v * v;
    }
    __shared__ float red[128];
    red[threadIdx.x] = s;
    __syncthreads();
    for (int st = 64; st > 0; st >>= 1) {
        if (threadIdx.x < st) red[threadIdx.x] += red[threadIdx.x + st];
        __syncthreads();
    }
    if (threadIdx.x == 0) xx[r] = red[0];
}

// K[n,m] = softmax_m((2*xy - xx[m]) / sigma)  (per-row constants dropped)
__global__ void softmax_kernel(float* __restrict__ xy,
                               const float* __restrict__ xx,
                               const float* __restrict__ sigma)
{
    const int row = blockIdx.x;
    const int b = row >> 7;
    const int t = threadIdx.x;
    const float inv_s = 1.0f / sigma[0];
    float* L = xy + (size_t)row * 128;

    float v = (2.0f * L[t] - xx[b * 128 + t]) * inv_s;

    __shared__ float red[128];
    red[t] = v;
    __syncthreads();
    for (int st = 64; st > 0; st >>= 1) {
        if (t < st) red[t] = fmaxf(red[t], red[t + st]);
        __syncthreads();
    }
    const float mx = red[0];
    __syncthreads();
    const float e = expf(v - mx);
    red[t] = e;
    __syncthreads();
    for (int st = 64; st > 0; st >>= 1) {
        if (t < st) red[t] += red[t + st];
        __syncthreads();
    }
    L[t] = e / red[0];
}

// out[b,n,t] = 0.5 * ( z[b,n,t] + sum_m K[b,n,m] * z[b,m,t] ), 8 rows/block
__global__ void mix_avg_kernel(const float* __restrict__ Kw,
                               const float* __restrict__ z,
                               float* __restrict__ out)
{
    const int b  = blockIdx.y;
    const int n0 = blockIdx.x * 8;
    const int t  = threadIdx.x;

    __shared__ float sK[8][128];
    const float* Kr = Kw + ((size_t)b * 128 + n0) * 128;
    for (int i = t; i < 8 * 128; i += 160) sK[i >> 7][i & 127] = Kr[i];
    __syncthreads();

    const float* zb = z + (size_t)b * 128 * 160;
    float acc[8] = {};
    #pragma unroll 4
    for (int m = 0; m < 128; ++m) {
        const float zv = zb[(size_t)m * 160 + t];
        #pragma unroll
        for (int j = 0; j < 8; ++j) acc[j] += sK[j][m] * zv;
    }
    #pragma unroll
    for (int j = 0; j < 8; ++j)
        out[((size_t)b * 128 + n0 + j) * 160 + t] =
            0.5f * (acc[j] + zb[(size_t)(n0 + j) * 160 + t]);
}

// out[b] = exp( sum_d max_n(H6[b,n,d]) * Wc[d] + bc )
__global__ void final_kernel(const float* __restrict__ H6,
                             const float* __restrict__ Wc,
                             const float* __restrict__ bc,
                             float* __restrict__ out)
{
    const int b = blockIdx.x;
    const int t = threadIdx.x;   // 160 threads = 5 warps
    float m = -3.0e38f;
    for (int n = 0; n < 128; ++n)
        m = fmaxf(m, H6[((size_t)b * 128 + n) * 160 + t]);
    float s = m * Wc[t];
    #pragma unroll
    for (int o = 16; o > 0; o >>= 1)
        s += __shfl_down_sync(0xFFFFFFFFu, s, o);
    __shared__ float red[5];
    if ((t & 31) == 0) red[t >> 5] = s;
    __syncthreads();
    if (t == 0) {
        float tot = red[0] + red[1] + red[2] + red[3] + red[4];
        out[b] = expf(tot + bc[0]);
    }
}

// ---------------------------------------------------------------------------
// Host launcher
// ---------------------------------------------------------------------------
extern "C" void kernel_launch(void* const* d_in, const int* in_sizes, int n_in,
                              void* d_out, int out_size)
{
    const float* H     = (const float*)d_in[0];
    const float* w1    = (const float*)d_in[1];
    const float* b1    = (const float*)d_in[2];
    const float* w2    = (const float*)d_in[3];
    const float* b2    = (const float*)d_in[4];
    const float* w3    = (const float*)d_in[5];
    const float* b3    = (const float*)d_in[6];
    const float* w4    = (const float*)d_in[7];
    const float* b4    = (const float*)d_in[8];
    const float* Wdk1  = (const float*)d_in[9];
    const float* bdk1  = (const float*)d_in[10];
    const float* Wdk2  = (const float*)d_in[11];
    const float* bdk2  = (const float*)d_in[12];
    const float* Wt1   = (const float*)d_in[13];
    const float* bt1   = (const float*)d_in[14];
    const float* Wt2   = (const float*)d_in[15];
    const float* bt2   = (const float*)d_in[16];
    const float* Wt3   = (const float*)d_in[17];
    const float* bt3   = (const float*)d_in[18];
    const float* sigma = (const float*)d_in[19];
    const float* Wc    = (const float*)d_in[20];
    const float* bc    = (const float*)d_in[21];

    float *p1, *p2, *hf, *dk1, *dkf, *xx, *Kp, *avg, *h2, *h4, *h6;
    cudaGetSymbolAddress((void**)&p1,  g_P1);
    cudaGetSymbolAddress((void**)&p2,  g_P2);
    cudaGetSymbolAddress((void**)&hf,  g_Hf);
    cudaGetSymbolAddress((void**)&dk1, g_dk1);
    cudaGetSymbolAddress((void**)&dkf, g_dkf);
    cudaGetSymbolAddress((void**)&xx,  g_xx);
    cudaGetSymbolAddress((void**)&Kp,  g_K);
    cudaGetSymbolAddress((void**)&avg, g_avg);
    cudaGetSymbolAddress((void**)&h2,  g_H2);
    cudaGetSymbolAddress((void**)&h4,  g_H4);
    cudaGetSymbolAddress((void**)&h6,  g_H6);

    const size_t smem1 = (1 * 100 * 100 + 90 + 10) * sizeof(float);          // 40.4 KB
    const size_t smem2 = (10 * 26 * 49 + 900 + 10) * sizeof(float);          // 54.6 KB
    const size_t smemf = (2 * 10 * 23 * 23 + 900 + 10 + 2 * 1000 + 900 + 10)
                         * sizeof(float);                                     // 57.6 KB
    cudaFuncSetAttribute(conv_pool_rows<10, 49, 160>,
                         cudaFuncAttributeMaxDynamicSharedMemorySize, (int)smem2);
    cudaFuncSetAttribute(conv34_fused<2, 128>,
                         cudaFuncAttributeMaxDynamicSharedMemorySize, (int)smemf);

    // ---- Conv stack ----
    conv_pool_pair<1, 100, 256><<<NIMG, 256, smem1>>>(H, w1, b1, p1);
    conv_pool_rows<10, 49, 160><<<dim3(NIMG, 2), 160, smem2>>>(p1, w2, b2, p2);
    conv34_fused<2, 128><<<NIMG / 2, 128, smemf>>>(p2, w3, b3, w4, b4, hf);

    // ---- Deep-kernel MLP ----
    gemm32<true, true><<<dim3(256 / 32, 1024 / 32), 64>>>(
        hf, Wdk1, bdk1, dk1, 1024, 256, 160, 0, 0, 0);
    gemm32<true, true><<<dim3(512 / 32, 1024 / 32), 64>>>(
        dk1, Wdk2, bdk2, dkf, 1024, 512, 256, 0, 0, 0);

    // ---- Attention matrix K (shared by all 3 message-passing rounds) ----
    rowsq_kernel<<<NIMG, 128>>>(dkf, xx);
    gemm32<false, false><<<dim3(4, 4, 8), 64>>>(
        dkf, dkf, nullptr, Kp, 128, 128, 512,
        128LL * 512, 128LL * 512, 128LL * 128);
    softmax_kernel<<<NIMG, 128>>>(Kp, xx, sigma);

    dim3 mixg(16, 8);

    // ---- Round 1 ----
    mix_avg_kernel<<<mixg, 160>>>(Kp, hf, avg);
    gemm32<true, true><<<dim3(160 / 32, 1024 / 32), 64>>>(
        avg, Wt1, bt1, h2, 1024, 160, 160, 0, 0, 0);

    // ---- Round 2 ----
    mix_avg_kernel<<<mixg, 160>>>(Kp, h2, avg);
    gemm32<true, true><<<dim3(160 / 32, 1024 / 32), 64>>>(
        avg, Wt2, bt2, h4, 1024, 160, 160, 0, 0, 0);

    // ---- Round 3 ----
    mix_avg_kernel<<<mixg, 160>>>(Kp, h4, avg);
    gemm32<true, true><<<dim3(160 / 32, 1024 / 32), 64>>>(
        avg, Wt3, bt3, h6, 1024, 160, 160, 0, 0, 0);

    // ---- Finish ----
    final_kernel<<<8, 160>>>(h6, Wc, bc, (float*)d_out);
}